// round 1
// baseline (speedup 1.0000x reference)
#include <cuda_runtime.h>

// Fixed problem shapes
#define T_STEPS 5
#define BS      32
#define C       64
#define H       64
#define W       64
#define VTH     1.0f
// gamma = DROP_RATE / BLOCK_SIZE^2 = 0.1 / 49
#define GAMMA   0.002040816326530612f

#define N_PLANES (T_STEPS * BS)               // 160
#define PLANE    (H * W)                      // 4096
#define CHW      (C * H * W)                  // 262144
#define ELEMS_PER_T (BS * C * H * W)          // 8388608
#define VEC_PER_T   (ELEMS_PER_T / 4)         // 2097152

// dropblock keep-mask scratch: [160, 64, 64] float (2.62 MB), static device mem
__device__ __align__(16) float d_bm[N_PLANES * PLANE];

// ---------------------------------------------------------------------------
// Kernel 1: block mask. One block per (t*bs) plane. Separable 7x7 max-pool
// (threshold -> horizontal max -> vertical max), all in shared memory.
// ---------------------------------------------------------------------------
__global__ void __launch_bounds__(256) block_mask_kernel(const float* __restrict__ mr) {
    __shared__ float sm[PLANE];   // thresholded
    __shared__ float sh[PLANE];   // horizontal max
    const int n = blockIdx.x;
    const float* p = mr + n * PLANE;

    for (int i = threadIdx.x; i < PLANE; i += 256)
        sm[i] = (p[i] < GAMMA) ? 1.0f : 0.0f;
    __syncthreads();

    // horizontal max over [w-3, w+3], clamped (reduce_window pads with -inf)
    for (int i = threadIdx.x; i < PLANE; i += 256) {
        const int h = i >> 6;
        const int w = i & 63;
        const int w0 = (w - 3 < 0) ? 0 : w - 3;
        const int w1 = (w + 3 > 63) ? 63 : w + 3;
        float m = 0.0f;
        #pragma unroll 7
        for (int ww = w0; ww <= w1; ++ww)
            m = fmaxf(m, sm[(h << 6) + ww]);
        sh[i] = m;
    }
    __syncthreads();

    // vertical max over [h-3, h+3], clamped; write keep-mask = 1 - pooled
    for (int i = threadIdx.x; i < PLANE; i += 256) {
        const int h = i >> 6;
        const int w = i & 63;
        const int h0 = (h - 3 < 0) ? 0 : h - 3;
        const int h1 = (h + 3 > 63) ? 63 : h + 3;
        float m = 0.0f;
        #pragma unroll 7
        for (int hh = h0; hh <= h1; ++hh)
            m = fmaxf(m, sh[(hh << 6) + w]);
        d_bm[n * PLANE + i] = 1.0f - m;
    }
}

// ---------------------------------------------------------------------------
// Kernel 2: LIF scan over T=5, vectorized float4 (4 consecutive w per thread).
// Each thread owns one (b, c, h, w4) site; u lives in registers.
//   u_new = (u > VTH) ? x : 0.5*u + x     (reset-to-zero leak)
//   o     = (u_new > VTH) ? bm : 0
// ---------------------------------------------------------------------------
__global__ void __launch_bounds__(256) lif_kernel(const float4* __restrict__ x,
                                                  float4* __restrict__ out) {
    const int v = blockIdx.x * 256 + threadIdx.x;
    if (v >= VEC_PER_T) return;

    // v = ((b*64 + c)*64 + h)*16 + wq
    const int wq = v & 15;
    const int h  = (v >> 4) & 63;
    const int b  = v >> 16;
    // bm float4 index for timestep t: ((t*BS + b)*64 + h)*16 + wq
    const int bm_base = ((b << 6) + h) * 16 + wq;
    const float4* __restrict__ bm4 = reinterpret_cast<const float4*>(d_bm);

    float4 u = make_float4(0.f, 0.f, 0.f, 0.f);

    #pragma unroll
    for (int t = 0; t < T_STEPS; ++t) {
        const float4 xt  = x[t * VEC_PER_T + v];
        const float4 bmt = bm4[(t * BS) * (PLANE / 4) + bm_base];
        float4 o;

        u.x = (u.x > VTH) ? xt.x : fmaf(0.5f, u.x, xt.x);
        u.y = (u.y > VTH) ? xt.y : fmaf(0.5f, u.y, xt.y);
        u.z = (u.z > VTH) ? xt.z : fmaf(0.5f, u.z, xt.z);
        u.w = (u.w > VTH) ? xt.w : fmaf(0.5f, u.w, xt.w);

        o.x = (u.x > VTH) ? bmt.x : 0.0f;
        o.y = (u.y > VTH) ? bmt.y : 0.0f;
        o.z = (u.z > VTH) ? bmt.z : 0.0f;
        o.w = (u.w > VTH) ? bmt.w : 0.0f;

        out[t * VEC_PER_T + v] = o;
    }
}

extern "C" void kernel_launch(void* const* d_in, const int* in_sizes, int n_in,
                              void* d_out, int out_size) {
    const float* x  = (const float*)d_in[0];
    const float* mr = (const float*)d_in[1];
    float* out      = (float*)d_out;

    block_mask_kernel<<<N_PLANES, 256>>>(mr);
    lif_kernel<<<(VEC_PER_T + 255) / 256, 256>>>(
        reinterpret_cast<const float4*>(x),
        reinterpret_cast<float4*>(out));
}